// round 10
// baseline (speedup 1.0000x reference)
#include <cuda_runtime.h>
#include <cuda_fp16.h>
#include <math.h>

#define DIMV   64
#define NEMB   512
#define TPB    512
#define TILE_M 128
#define ROWB   144          // padded row stride: 72 fp16 (conflict-free ldmatrix)

// ---------------- smem layout (bytes) ----------------
#define B_HI_OFF   0                          // 512 x 144B fp16 (-2w hi)
#define A_HI_OFF   (512*ROWB)                 // 73728, 128 x 144B
#define STAGE0_OFF (A_HI_OFF + 128*ROWB)      // 92160, raw fp32 tile 32KB
#define STAGE1_OFF (STAGE0_OFF + 32768)       // 124928, second ring buffer
#define SWSQ_OFF   (STAGE1_OFF + 32768)       // 157696, 512 f32
#define SCNT_OFF   (SWSQ_OFF + 2048)          // 512 f32
#define SXSQ_OFF   (SCNT_OFF + 2048)          // 128 f32
#define SKEY_OFF   (SXSQ_OFF + 512)           // 2 x 128 x 2 u32 = 2048
#define SJ_OFF     (SKEY_OFF + 2048)          // 128 i32
#define SLOSS_OFF  (SJ_OFF + 512)
#define SMEM_BYTES (SLOSS_OFF + 16)           // 164880

// ---------------- device scratch ----------------
__device__ float          g_wsq[NEMB];
__device__ unsigned short g_w_hi[NEMB * DIMV];   // [j][k], -2w fp16 hi
__device__ unsigned short g_w_lo[NEMB * DIMV];   // fp16 residual (refine reads global)
__device__ __align__(16) float g_embed_sum[NEMB * DIMV];  // code-major [j][k]
__device__ float          g_counts[NEMB];
__device__ float          g_inv[NEMB];
__device__ float          g_loss_sum;

// ---------------- helpers ----------------
__device__ __forceinline__ unsigned smem_u32(const void* p) {
    unsigned a;
    asm("{ .reg .u64 t; cvta.to.shared.u64 t, %1; cvt.u32.u64 %0, t; }" : "=r"(a) : "l"(p));
    return a;
}
__device__ __forceinline__ unsigned ford(float f) {
    unsigned u = __float_as_uint(f);
    unsigned m = (unsigned)((int)u >> 31) | 0x80000000u;
    return u ^ m;
}
__device__ __forceinline__ unsigned long long packkey(float v, int j) {
    return ((unsigned long long)ford(v) << 32) | (unsigned)j;
}
__device__ __forceinline__ unsigned umn(unsigned a, unsigned b) { return a < b ? a : b; }
__device__ __forceinline__ unsigned umx(unsigned a, unsigned b) { return a > b ? a : b; }
__device__ __forceinline__ unsigned long long u64min(unsigned long long a, unsigned long long b) {
    return a < b ? a : b;
}
__device__ __forceinline__ void ldm_x4(unsigned &r0, unsigned &r1, unsigned &r2, unsigned &r3,
                                       unsigned addr) {
    asm volatile("ldmatrix.sync.aligned.m8n8.x4.shared.b16 {%0,%1,%2,%3}, [%4];"
                 : "=r"(r0), "=r"(r1), "=r"(r2), "=r"(r3) : "r"(addr));
}
__device__ __forceinline__ void mma_fp16(float* d, const unsigned* a, unsigned b0, unsigned b1) {
    asm volatile("mma.sync.aligned.m16n8k16.row.col.f32.f16.f16.f32 "
                 "{%0,%1,%2,%3},{%4,%5,%6,%7},{%8,%9},{%0,%1,%2,%3};"
                 : "+f"(d[0]), "+f"(d[1]), "+f"(d[2]), "+f"(d[3])
                 : "r"(a[0]), "r"(a[1]), "r"(a[2]), "r"(a[3]), "r"(b0), "r"(b1));
}
__device__ __forceinline__ void red_add_v4(float* p, float a, float b, float c, float d) {
    asm volatile("red.global.add.v4.f32 [%0], {%1,%2,%3,%4};"
                 :: "l"(p), "f"(a), "f"(b), "f"(c), "f"(d) : "memory");
}
__device__ __forceinline__ void cp_async16(unsigned dst, const void* src) {
    asm volatile("cp.async.cg.shared.global [%0], [%1], 16;" :: "r"(dst), "l"(src) : "memory");
}
#define CP_COMMIT() asm volatile("cp.async.commit_group;" ::: "memory")
#define CP_WAIT1()  asm volatile("cp.async.wait_group 1;" ::: "memory")
#define CP_WAIT0()  asm volatile("cp.async.wait_group 0;" ::: "memory")
__device__ __forceinline__ float2 h2f2(unsigned u) {
    __half2 h = *(__half2*)&u;
    return __half22float2(h);
}

// ---------------------------------------------------------------------------
// Kernel 1: coalesced init via smem transpose.
// Blocks 0-7: codebook (64 codes each). Blocks 8-71: zero embed_sum/counts.
// ---------------------------------------------------------------------------
__global__ void vq_init(const float* __restrict__ w) {
    const int b = blockIdx.x;
    const int tid = threadIdx.x;

    if (b >= 8) {
        int idx = (b - 8) * 256 + tid;       // 0..16383
        ((float2*)g_embed_sum)[idx] = make_float2(0.0f, 0.0f);
        if (idx < NEMB) g_counts[idx] = 0.0f;
        if (b == 8 && tid == 0) g_loss_sum = 0.0f;
        return;
    }

    __shared__ float t[DIMV][65];            // transposed tile, padded
#pragma unroll
    for (int i = 0; i < 16; i++) {
        int idx = tid + i * 256;             // 0..4095
        int k = idx >> 6, jl = idx & 63;
        t[k][jl] = w[k * NEMB + b * 64 + jl];
    }
    __syncthreads();

    const int jl = tid >> 2;
    const int kb = (tid & 3) * 16;
    const int j  = b * 64 + jl;

    unsigned hi[8], lo[8];
    float s = 0.0f;
#pragma unroll
    for (int c = 0; c < 16; c += 2) {
        float v0 = t[kb + c][jl], v1 = t[kb + c + 1][jl];
        s = fmaf(v0, v0, fmaf(v1, v1, s));
        float m0 = -2.0f * v0, m1 = -2.0f * v1;
        __half h0 = __float2half_rn(m0), h1 = __float2half_rn(m1);
        __half l0 = __float2half_rn(m0 - __half2float(h0));
        __half l1 = __float2half_rn(m1 - __half2float(h1));
        hi[c >> 1] = __half_as_ushort(h0) | ((unsigned)__half_as_ushort(h1) << 16);
        lo[c >> 1] = __half_as_ushort(l0) | ((unsigned)__half_as_ushort(l1) << 16);
    }
    uint4* dhi = (uint4*)(g_w_hi + j * DIMV + kb);
    uint4* dlo = (uint4*)(g_w_lo + j * DIMV + kb);
    dhi[0] = make_uint4(hi[0], hi[1], hi[2], hi[3]);
    dhi[1] = make_uint4(hi[4], hi[5], hi[6], hi[7]);
    dlo[0] = make_uint4(lo[0], lo[1], lo[2], lo[3]);
    dlo[1] = make_uint4(lo[4], lo[5], lo[6], lo[7]);

    s += __shfl_xor_sync(0xFFFFFFFFu, s, 1);
    s += __shfl_xor_sync(0xFFFFFFFFu, s, 2);
    if ((tid & 3) == 0) g_wsq[j] = s;
}

// ---------------------------------------------------------------------------
// Kernel 2: persistent main — fp16 screen (positive u32 keys) + exact refine
// ---------------------------------------------------------------------------
__global__ __launch_bounds__(TPB, 1)
void vq_main(const float* __restrict__ inp, int nrows) {
    extern __shared__ __align__(1024) char sm[];
    const unsigned sbase = smem_u32(sm);
    const int tid  = threadIdx.x;
    const int lane = tid & 31;
    const int wid  = tid >> 5;
    const int mgrp = wid >> 1;      // 0..7 : row group of 16
    const int nh   = wid & 1;       // 0..1 : code half of 256

    float* swsq  = (float*)(sm + SWSQ_OFF);
    float* scnt  = (float*)(sm + SCNT_OFF);
    float* sxsq  = (float*)(sm + SXSQ_OFF);
    unsigned* skey = (unsigned*)(sm + SKEY_OFF);
    int*   sj    = (int*)(sm + SJ_OFF);
    float* sloss = (float*)(sm + SLOSS_OFF);

    // --- stage B_HI into padded rows + swsq + zero counters ---
    {
        const uint4* srcH = (const uint4*)g_w_hi;
#pragma unroll
        for (int i = 0; i < 8; i++) {
            int idx = tid + i * TPB;        // 0..4095 : 16B chunk index
            int row = idx >> 3, c = idx & 7;
            *(uint4*)(sm + B_HI_OFF + row * ROWB + c * 16) = srcH[idx];
        }
        swsq[tid] = g_wsq[tid];
        scnt[tid] = 0.0f;
        if (tid == 0) *sloss = 0.0f;
    }

    // lane-fixed ldmatrix address offsets
    const unsigned aoff = (unsigned)((lane & 15) * ROWB + (lane >> 4) * 16);
    const unsigned boff = (unsigned)(((lane & 7) + ((lane >> 4) << 3)) * ROWB + ((lane >> 3) & 1) * 16);
    const unsigned aHbase = sbase + A_HI_OFF + (unsigned)(mgrp * 16 * ROWB) + aoff;
    const unsigned bHbase = sbase + B_HI_OFF + (unsigned)(nh * 256 * ROWB) + boff;

    float loss_acc = 0.0f;
    const int nchunks = nrows / TILE_M;
    const unsigned stg_off[2] = {STAGE0_OFF, STAGE1_OFF};
    int p = 0;

    // ---- prefetch first tile into staging[0] ----
    {
        const float4* src = (const float4*)inp + (size_t)blockIdx.x * (TILE_M * DIMV / 4);
#pragma unroll
        for (int i = 0; i < 4; i++)
            cp_async16(sbase + STAGE0_OFF + (tid + i * TPB) * 16, src + tid + i * TPB);
        CP_COMMIT();
    }

    for (int tile = blockIdx.x; tile < nchunks; tile += gridDim.x) {
        CP_WAIT0();
        __syncthreads();   // S1: staging[p] visible; prev refine/scatter done

        const float4* stg = (const float4*)(sm + stg_off[p]);

        // ---- convert x -> fp16 hi in smem + ||x||^2 ----
#pragma unroll
        for (int i = 0; i < 4; i++) {
            int idx = tid + i * TPB;
            float4 x = stg[idx];
            __half2 a = __float22half2_rn(make_float2(x.x, x.y));
            __half2 b = __float22half2_rn(make_float2(x.z, x.w));
            unsigned long long hw = ((unsigned long long)(*(unsigned*)&b) << 32) | (*(unsigned*)&a);
            int row = idx >> 4, kc = idx & 15;
            *(unsigned long long*)(sm + A_HI_OFF + row * ROWB + kc * 8) = hw;
            float pq = fmaf(x.x, x.x, fmaf(x.y, x.y, fmaf(x.z, x.z, x.w * x.w)));
#pragma unroll
            for (int m = 1; m < 16; m <<= 1) pq += __shfl_xor_sync(0xFFFFFFFFu, pq, m);
            if ((lane & 15) == 0) sxsq[row] = pq;
        }
        __syncthreads();   // S2: A_HI + sxsq ready

        // ---- prefetch next tile into the other ring buffer (overlaps MMA) ----
        {
            int nxt = tile + gridDim.x;
            if (nxt < nchunks) {
                const float4* src = (const float4*)inp + (size_t)nxt * (TILE_M * DIMV / 4);
#pragma unroll
                for (int i = 0; i < 4; i++)
                    cp_async16(sbase + stg_off[p ^ 1] + (tid + i * TPB) * 16, src + tid + i * TPB);
            }
            CP_COMMIT();
        }

        // ---- load A hi fragments ----
        unsigned Ah[4][4];
#pragma unroll
        for (int ks = 0; ks < 4; ks++)
            ldm_x4(Ah[ks][0], Ah[ks][1], Ah[ks][2], Ah[ks][3], aHbase + (unsigned)(ks * 32));

        // per-slot ||x||^2 (rows owned by this thread's quad position)
        const int r0 = mgrp * 16 + (lane >> 2);
        const float xq0 = sxsq[r0], xq1 = sxsq[r0 + 8];

        // ---- screen GEMM; positive-key top-2 (pure IMNMX/LOP3) ----
        unsigned bk1[2] = {0xFFFFFFFFu, 0xFFFFFFFFu};
        unsigned bk2[2] = {0xFFFFFFFFu, 0xFFFFFFFFu};

#pragma unroll
        for (int chunk = 0; chunk < 4; chunk++) {
            float acc[8][4];
            int jb0 = nh * 256 + chunk * 64 + (lane & 3) * 2;
#pragma unroll
            for (int nt = 0; nt < 8; nt++) {
                float2 wq = *(float2*)(swsq + jb0 + nt * 8);
                acc[nt][0] = wq.x + xq0; acc[nt][1] = wq.y + xq0;
                acc[nt][2] = wq.x + xq1; acc[nt][3] = wq.y + xq1;
            }
            unsigned bc = (unsigned)(chunk * 64 * ROWB);
#pragma unroll
            for (int ks = 0; ks < 4; ks++) {
                unsigned B0[4][4];
#pragma unroll
                for (int pr = 0; pr < 4; pr++) {
                    unsigned off = bc + (unsigned)(pr * 16 * ROWB + ks * 32);
                    ldm_x4(B0[pr][0], B0[pr][1], B0[pr][2], B0[pr][3], bHbase + off);
                }
#pragma unroll
                for (int pr = 0; pr < 4; pr++) {
                    mma_fp16(acc[2*pr],   Ah[ks], B0[pr][0], B0[pr][1]);
                    mma_fp16(acc[2*pr+1], Ah[ks], B0[pr][2], B0[pr][3]);
                }
            }
            // fold: values are true sq-distances (>=0) -> bits order as unsigned
#pragma unroll
            for (int nt = 0; nt < 8; nt++) {
                int jb = jb0 + nt * 8;
#pragma unroll
                for (int q = 0; q < 4; q++) {
                    int s = q >> 1;
                    unsigned key = (__float_as_uint(acc[nt][q]) & ~0x1FFu) | (unsigned)(jb + (q & 1));
                    unsigned t = umx(bk1[s], key);
                    bk1[s] = umn(bk1[s], key);
                    bk2[s] = umn(bk2[s], t);
                }
            }
        }

        // ---- quad-merge u32 top-2, owners write per-half keys ----
#pragma unroll
        for (int s = 0; s < 2; s++) {
            unsigned k1 = bk1[s], k2 = bk2[s];
#pragma unroll
            for (int off = 1; off <= 2; off <<= 1) {
                unsigned o1 = __shfl_xor_sync(0xFFFFFFFFu, k1, off);
                unsigned o2 = __shfl_xor_sync(0xFFFFFFFFu, k2, off);
                unsigned t = umx(k1, o1);
                k1 = umn(k1, o1);
                k2 = umn(k2, umn(o2, t));
            }
            if ((lane & 3) == 0) {
                int r = mgrp * 16 + (lane >> 2) + s * 8;
                skey[(nh * 128 + r) * 2]     = k1;
                skey[(nh * 128 + r) * 2 + 1] = k2;
            }
        }
        __syncthreads();   // S3: both halves' top-2 keys in smem

        // ---- exact refine: 2 candidates/row; x fp32 from staging,
        //      w = smem B_HI + global g_w_lo residual ----
        if (tid < 2 * TILE_M) {
            int r = tid >> 1;
            unsigned ka1 = skey[r * 2],         ka2 = skey[r * 2 + 1];
            unsigned kb1 = skey[(128 + r) * 2], kb2 = skey[(128 + r) * 2 + 1];
            unsigned m1 = umn(ka1, kb1);
            unsigned m2 = umn(umx(ka1, kb1), umn(ka2, kb2));
            int j = (int)(((tid & 1) ? m2 : m1) & 0x1FFu);

            const float4* xr  = stg + r * 16;
            const uint4*  wh4 = (const uint4*)(sm + B_HI_OFF + j * ROWB);
            const uint4*  wl4 = (const uint4*)(g_w_lo + j * DIMV);
            float d = swsq[j];
#pragma unroll
            for (int c = 0; c < 8; c++) {
                uint4 hw = wh4[c], lw = wl4[c];
                float4 x0 = xr[c * 2], x1 = xr[c * 2 + 1];
                const unsigned hws[4] = {hw.x, hw.y, hw.z, hw.w};
                const unsigned lws[4] = {lw.x, lw.y, lw.z, lw.w};
                const float xs[8] = {x0.x, x0.y, x0.z, x0.w, x1.x, x1.y, x1.z, x1.w};
#pragma unroll
                for (int u = 0; u < 4; u++) {
                    float2 wa = h2f2(hws[u]), wb = h2f2(lws[u]);
                    d = fmaf(xs[u * 2],     wa.x + wb.x, d);
                    d = fmaf(xs[u * 2 + 1], wa.y + wb.y, d);
                }
            }
            unsigned long long kd = packkey(d, j);
            unsigned long long ko = __shfl_xor_sync(0xFFFFFFFFu, kd, 1);
            if ((tid & 1) == 0) {
                unsigned long long kw = u64min(kd, ko);
                int jw = (int)(kw & 0xFFFFFFFFull);
                float dw;
                { unsigned m = (unsigned)(kw >> 32);
                  unsigned uu = (m & 0x80000000u) ? (m ^ 0x80000000u) : ~m;
                  dw = __uint_as_float(uu); }
                sj[r] = jw;
                loss_acc += dw + sxsq[r];
                atomicAdd(&scnt[jw], 1.0f);
            }
        }
        __syncthreads();   // S4: sj ready

        // ---- embed_sum scatter from staging fp32 ----
#pragma unroll
        for (int i = 0; i < 4; i++) {
            int idx = tid + i * TPB;
            int r = idx >> 4;
            int j = sj[r];
            float4 x = stg[idx];
            red_add_v4(g_embed_sum + j * DIMV + (idx & 15) * 4, x.x, x.y, x.z, x.w);
        }
        p ^= 1;
    }

    // ---- flush block-local accumulators ----
    atomicAdd(sloss, loss_acc);
    __syncthreads();
    if (scnt[tid] != 0.0f) atomicAdd(&g_counts[tid], scnt[tid]);
    if (tid == 0) atomicAdd(&g_loss_sum, *sloss);
}

// ---------------------------------------------------------------------------
// Kernel 3a: scalar reductions — n, per-code inv factor, loss, perplexity, cs
// ---------------------------------------------------------------------------
__global__ void vq_final1(const float* __restrict__ cs_in,
                          float* __restrict__ out, int nrows) {
    __shared__ float red[NEMB];
    int j = threadIdx.x;

    float counts = g_counts[j];
    float ncs = fmaf(0.99f, cs_in[j], 0.01f * counts);

    red[j] = ncs;
    __syncthreads();
#pragma unroll
    for (int off = NEMB / 2; off; off >>= 1) {
        if (j < off) red[j] += red[j + off];
        __syncthreads();
    }
    float n = red[0];
    __syncthreads();

    float csj = (ncs + 1e-5f) / (n + (float)NEMB * 1e-5f) * n;
    g_inv[j] = 1.0f / csj;
    out[2 + DIMV * NEMB + j] = ncs;  // new_cluster_size

    float p = counts / (float)nrows;
    red[j] = p * logf(p + 1e-10f);
    __syncthreads();
#pragma unroll
    for (int off = NEMB / 2; off; off >>= 1) {
        if (j < off) red[j] += red[j + off];
        __syncthreads();
    }
    if (j == 0) {
        out[1] = expf(-red[0]);
        out[0] = 0.25f * g_loss_sum / ((float)nrows * (float)DIMV);
    }
}

// ---------------------------------------------------------------------------
// Kernel 3b: parallel output writer — new_embed_avg + new_w
// ---------------------------------------------------------------------------
__global__ void vq_final2(const float* __restrict__ ea_in, float* __restrict__ out) {
    int gid = blockIdx.x * blockDim.x + threadIdx.x;   // 0 .. 32767
    int k = gid >> 9, j = gid & (NEMB - 1);
    float ea = fmaf(0.99f, ea_in[gid], 0.01f * g_embed_sum[j * DIMV + k]);
    const int EA_OFF = 2 + DIMV * NEMB + NEMB;
    out[EA_OFF + gid] = ea;              // new_embed_avg
    out[2 + gid] = ea * g_inv[j];        // new_w
}

// ---------------------------------------------------------------------------
extern "C" void kernel_launch(void* const* d_in, const int* in_sizes, int n_in,
                              void* d_out, int out_size) {
    const float* inp = (const float*)d_in[0];
    const float* w   = (const float*)d_in[1];
    const float* cs  = (const float*)d_in[2];
    const float* ea  = (const float*)d_in[3];
    int nrows = in_sizes[0] / DIMV;

    cudaFuncSetAttribute(vq_main, cudaFuncAttributeMaxDynamicSharedMemorySize, SMEM_BYTES);

    vq_init<<<72, 256>>>(w);
    vq_main<<<148, TPB, SMEM_BYTES>>>(inp, nrows);
    vq_final1<<<1, NEMB>>>(cs, (float*)d_out, nrows);
    vq_final2<<<DIMV * NEMB / 256, 256>>>(ea, (float*)d_out);
}

// round 11
// speedup vs baseline: 1.1904x; 1.1904x over previous
#include <cuda_runtime.h>
#include <cuda_fp16.h>
#include <math.h>

#define DIMV   64
#define NEMB   512
#define TPB    512
#define TILE_M 128
#define ROWB   144          // padded row stride: 72 fp16 (conflict-free ldmatrix)

// ---------------- smem layout (bytes) ----------------
#define B_HI_OFF   0                          // 512 x 144B fp16 (-2w hi)
#define B_LO_OFF   (512*ROWB)                 // 73728
#define A_HI_OFF   (2*512*ROWB)               // 147456, 128 x 144B
#define A_LO_OFF   (A_HI_OFF + 128*ROWB)      // 165888
#define STAGE_OFF  (A_LO_OFF + 128*ROWB)      // 184320, raw fp32 tile 32KB
#define SWSQ_OFF   (STAGE_OFF + 32768)        // 217088, 512 f32
#define SCNT_OFF   (SWSQ_OFF + 2048)          // 512 f32
#define SXSQ_OFF   (SCNT_OFF + 2048)          // 128 f32
#define SKEY_OFF   (SXSQ_OFF + 512)           // 2 x 128 x 2 u32 = 2048
#define SJ_OFF     (SKEY_OFF + 2048)          // 128 i32
#define SLOSS_OFF  (SJ_OFF + 512)
#define SMEM_BYTES (SLOSS_OFF + 16)           // 224272

// ---------------- device scratch ----------------
__device__ float          g_wsq[NEMB];
__device__ unsigned short g_w_hi[NEMB * DIMV];   // [j][k], -2w fp16 hi
__device__ unsigned short g_w_lo[NEMB * DIMV];   // fp16 residual
__device__ __align__(16) float g_embed_sum[NEMB * DIMV];  // code-major [j][k]
__device__ float          g_counts[NEMB];
__device__ float          g_inv[NEMB];
__device__ float          g_loss_sum;

// ---------------- helpers ----------------
__device__ __forceinline__ unsigned smem_u32(const void* p) {
    unsigned a;
    asm("{ .reg .u64 t; cvta.to.shared.u64 t, %1; cvt.u32.u64 %0, t; }" : "=r"(a) : "l"(p));
    return a;
}
__device__ __forceinline__ unsigned ford(float f) {
    unsigned u = __float_as_uint(f);
    unsigned m = (unsigned)((int)u >> 31) | 0x80000000u;
    return u ^ m;
}
__device__ __forceinline__ unsigned long long packkey(float v, int j) {
    return ((unsigned long long)ford(v) << 32) | (unsigned)j;
}
__device__ __forceinline__ unsigned umn(unsigned a, unsigned b) { return a < b ? a : b; }
__device__ __forceinline__ unsigned umx(unsigned a, unsigned b) { return a > b ? a : b; }
__device__ __forceinline__ unsigned long long u64min(unsigned long long a, unsigned long long b) {
    return a < b ? a : b;
}
__device__ __forceinline__ void ldm_x4(unsigned &r0, unsigned &r1, unsigned &r2, unsigned &r3,
                                       unsigned addr) {
    asm volatile("ldmatrix.sync.aligned.m8n8.x4.shared.b16 {%0,%1,%2,%3}, [%4];"
                 : "=r"(r0), "=r"(r1), "=r"(r2), "=r"(r3) : "r"(addr));
}
__device__ __forceinline__ void mma_fp16(float* d, const unsigned* a, unsigned b0, unsigned b1) {
    asm volatile("mma.sync.aligned.m16n8k16.row.col.f32.f16.f16.f32 "
                 "{%0,%1,%2,%3},{%4,%5,%6,%7},{%8,%9},{%0,%1,%2,%3};"
                 : "+f"(d[0]), "+f"(d[1]), "+f"(d[2]), "+f"(d[3])
                 : "r"(a[0]), "r"(a[1]), "r"(a[2]), "r"(a[3]), "r"(b0), "r"(b1));
}
__device__ __forceinline__ void red_add_v4(float* p, float a, float b, float c, float d) {
    asm volatile("red.global.add.v4.f32 [%0], {%1,%2,%3,%4};"
                 :: "l"(p), "f"(a), "f"(b), "f"(c), "f"(d) : "memory");
}
__device__ __forceinline__ void cp_async16(unsigned dst, const void* src) {
    asm volatile("cp.async.cg.shared.global [%0], [%1], 16;" :: "r"(dst), "l"(src) : "memory");
}
#define CP_COMMIT() asm volatile("cp.async.commit_group;" ::: "memory")
#define CP_WAIT0()  asm volatile("cp.async.wait_group 0;" ::: "memory")
__device__ __forceinline__ float2 h2f2(unsigned u) {
    __half2 h = *(__half2*)&u;
    return __half22float2(h);
}

// ---------------------------------------------------------------------------
// Kernel 1: coalesced init via smem transpose.
// Blocks 0-7: codebook (64 codes each). Blocks 8-71: zero embed_sum/counts.
// ---------------------------------------------------------------------------
__global__ void vq_init(const float* __restrict__ w) {
    const int b = blockIdx.x;
    const int tid = threadIdx.x;

    if (b >= 8) {
        int idx = (b - 8) * 256 + tid;       // 0..16383
        ((float2*)g_embed_sum)[idx] = make_float2(0.0f, 0.0f);
        if (idx < NEMB) g_counts[idx] = 0.0f;
        if (b == 8 && tid == 0) g_loss_sum = 0.0f;
        return;
    }

    __shared__ float t[DIMV][65];            // transposed tile, padded
#pragma unroll
    for (int i = 0; i < 16; i++) {
        int idx = tid + i * 256;             // 0..4095
        int k = idx >> 6, jl = idx & 63;
        t[k][jl] = w[k * NEMB + b * 64 + jl];
    }
    __syncthreads();

    const int jl = tid >> 2;
    const int kb = (tid & 3) * 16;
    const int j  = b * 64 + jl;

    unsigned hi[8], lo[8];
    float s = 0.0f;
#pragma unroll
    for (int c = 0; c < 16; c += 2) {
        float v0 = t[kb + c][jl], v1 = t[kb + c + 1][jl];
        s = fmaf(v0, v0, fmaf(v1, v1, s));
        float m0 = -2.0f * v0, m1 = -2.0f * v1;
        __half h0 = __float2half_rn(m0), h1 = __float2half_rn(m1);
        __half l0 = __float2half_rn(m0 - __half2float(h0));
        __half l1 = __float2half_rn(m1 - __half2float(h1));
        hi[c >> 1] = __half_as_ushort(h0) | ((unsigned)__half_as_ushort(h1) << 16);
        lo[c >> 1] = __half_as_ushort(l0) | ((unsigned)__half_as_ushort(l1) << 16);
    }
    uint4* dhi = (uint4*)(g_w_hi + j * DIMV + kb);
    uint4* dlo = (uint4*)(g_w_lo + j * DIMV + kb);
    dhi[0] = make_uint4(hi[0], hi[1], hi[2], hi[3]);
    dhi[1] = make_uint4(hi[4], hi[5], hi[6], hi[7]);
    dlo[0] = make_uint4(lo[0], lo[1], lo[2], lo[3]);
    dlo[1] = make_uint4(lo[4], lo[5], lo[6], lo[7]);

    s += __shfl_xor_sync(0xFFFFFFFFu, s, 1);
    s += __shfl_xor_sync(0xFFFFFFFFu, s, 2);
    if ((tid & 3) == 0) g_wsq[j] = s;
}

// ---------------------------------------------------------------------------
// Kernel 2: persistent main — fp16 HMMA screen (positive u32 keys) + refine
// ---------------------------------------------------------------------------
__global__ __launch_bounds__(TPB, 1)
void vq_main(const float* __restrict__ inp, int nrows) {
    extern __shared__ __align__(1024) char sm[];
    const unsigned sbase = smem_u32(sm);
    const int tid  = threadIdx.x;
    const int lane = tid & 31;
    const int wid  = tid >> 5;
    const int mgrp = wid >> 1;      // 0..7 : row group of 16
    const int nh   = wid & 1;       // 0..1 : code half of 256

    float* swsq  = (float*)(sm + SWSQ_OFF);
    float* scnt  = (float*)(sm + SCNT_OFF);
    float* sxsq  = (float*)(sm + SXSQ_OFF);
    unsigned* skey = (unsigned*)(sm + SKEY_OFF);
    int*   sj    = (int*)(sm + SJ_OFF);
    float* sloss = (float*)(sm + SLOSS_OFF);

    // --- stage B (-2w hi/lo fp16) into padded rows + swsq + zero counters ---
    {
        const uint4* srcH = (const uint4*)g_w_hi;
        const uint4* srcL = (const uint4*)g_w_lo;
#pragma unroll
        for (int i = 0; i < 8; i++) {
            int idx = tid + i * TPB;        // 0..4095 : 16B chunk index
            int row = idx >> 3, c = idx & 7;
            *(uint4*)(sm + B_HI_OFF + row * ROWB + c * 16) = srcH[idx];
            *(uint4*)(sm + B_LO_OFF + row * ROWB + c * 16) = srcL[idx];
        }
        swsq[tid] = g_wsq[tid];
        scnt[tid] = 0.0f;
        if (tid == 0) *sloss = 0.0f;
    }

    // lane-fixed ldmatrix address offsets
    const unsigned aoff = (unsigned)((lane & 15) * ROWB + (lane >> 4) * 16);
    const unsigned boff = (unsigned)(((lane & 7) + ((lane >> 4) << 3)) * ROWB + ((lane >> 3) & 1) * 16);
    const unsigned aHbase = sbase + A_HI_OFF + (unsigned)(mgrp * 16 * ROWB) + aoff;
    const unsigned bHbase = sbase + B_HI_OFF + (unsigned)(nh * 256 * ROWB) + boff;

    float loss_acc = 0.0f;
    const int nchunks = nrows / TILE_M;

    // ---- prefetch first tile into staging ----
    {
        const float4* src = (const float4*)inp + (size_t)blockIdx.x * (TILE_M * DIMV / 4);
#pragma unroll
        for (int i = 0; i < 4; i++)
            cp_async16(sbase + STAGE_OFF + (tid + i * TPB) * 16, src + tid + i * TPB);
        CP_COMMIT();
    }

    for (int tile = blockIdx.x; tile < nchunks; tile += gridDim.x) {
        CP_WAIT0();
        __syncthreads();   // S1: staging visible; prev refine/scatter done

        // ---- convert x -> fp16 hi/lo in smem + ||x||^2 (x kept in v regs) ----
        float4 v[4];
        const float4* stg = (const float4*)(sm + STAGE_OFF);
#pragma unroll
        for (int i = 0; i < 4; i++) {
            int idx = tid + i * TPB;
            float4 x = stg[idx];
            v[i] = x;
            __half h0 = __float2half_rn(x.x), h1 = __float2half_rn(x.y);
            __half h2 = __float2half_rn(x.z), h3 = __float2half_rn(x.w);
            __half l0 = __float2half_rn(x.x - __half2float(h0));
            __half l1 = __float2half_rn(x.y - __half2float(h1));
            __half l2 = __float2half_rn(x.z - __half2float(h2));
            __half l3 = __float2half_rn(x.w - __half2float(h3));
            unsigned hw0 = __half_as_ushort(h0) | ((unsigned)__half_as_ushort(h1) << 16);
            unsigned hw1 = __half_as_ushort(h2) | ((unsigned)__half_as_ushort(h3) << 16);
            unsigned lw0 = __half_as_ushort(l0) | ((unsigned)__half_as_ushort(l1) << 16);
            unsigned lw1 = __half_as_ushort(l2) | ((unsigned)__half_as_ushort(l3) << 16);
            unsigned long long hw = ((unsigned long long)hw1 << 32) | hw0;
            unsigned long long lw = ((unsigned long long)lw1 << 32) | lw0;
            int row = idx >> 4, kc = idx & 15;
            *(unsigned long long*)(sm + A_HI_OFF + row * ROWB + kc * 8) = hw;
            *(unsigned long long*)(sm + A_LO_OFF + row * ROWB + kc * 8) = lw;
            float pq = fmaf(x.x, x.x, fmaf(x.y, x.y, fmaf(x.z, x.z, x.w * x.w)));
#pragma unroll
            for (int m = 1; m < 16; m <<= 1) pq += __shfl_xor_sync(0xFFFFFFFFu, pq, m);
            if ((lane & 15) == 0) sxsq[row] = pq;
        }
        __syncthreads();   // S2: A smem + sxsq ready; staging reads done

        // ---- prefetch next tile (overlaps MMA) ----
        {
            int nxt = tile + gridDim.x;
            if (nxt < nchunks) {
                const float4* src = (const float4*)inp + (size_t)nxt * (TILE_M * DIMV / 4);
#pragma unroll
                for (int i = 0; i < 4; i++)
                    cp_async16(sbase + STAGE_OFF + (tid + i * TPB) * 16, src + tid + i * TPB);
            }
            CP_COMMIT();
        }

        // ---- load A hi fragments ----
        unsigned Ah[4][4];
#pragma unroll
        for (int ks = 0; ks < 4; ks++)
            ldm_x4(Ah[ks][0], Ah[ks][1], Ah[ks][2], Ah[ks][3], aHbase + (unsigned)(ks * 32));

        // per-slot ||x||^2 (rows owned by this thread's quad position)
        const int r0 = mgrp * 16 + (lane >> 2);
        const float xq0 = sxsq[r0], xq1 = sxsq[r0 + 8];

        // ---- single-pass screen GEMM; positive-key top-2 (pure IMNMX/LOP3) ----
        unsigned bk1[2] = {0xFFFFFFFFu, 0xFFFFFFFFu};
        unsigned bk2[2] = {0xFFFFFFFFu, 0xFFFFFFFFu};

#pragma unroll
        for (int chunk = 0; chunk < 4; chunk++) {
            float acc[8][4];
            int jb0 = nh * 256 + chunk * 64 + (lane & 3) * 2;
#pragma unroll
            for (int nt = 0; nt < 8; nt++) {
                float2 wq = *(float2*)(swsq + jb0 + nt * 8);
                acc[nt][0] = wq.x + xq0; acc[nt][1] = wq.y + xq0;
                acc[nt][2] = wq.x + xq1; acc[nt][3] = wq.y + xq1;
            }
            unsigned bc = (unsigned)(chunk * 64 * ROWB);
#pragma unroll
            for (int ks = 0; ks < 4; ks++) {
                unsigned B0[4][4];
#pragma unroll
                for (int pr = 0; pr < 4; pr++) {
                    unsigned off = bc + (unsigned)(pr * 16 * ROWB + ks * 32);
                    ldm_x4(B0[pr][0], B0[pr][1], B0[pr][2], B0[pr][3], bHbase + off);
                }
#pragma unroll
                for (int pr = 0; pr < 4; pr++) {
                    mma_fp16(acc[2*pr],   Ah[ks], B0[pr][0], B0[pr][1]);
                    mma_fp16(acc[2*pr+1], Ah[ks], B0[pr][2], B0[pr][3]);
                }
            }
            // fold: values are true sq-distances (>=0) -> bits order as unsigned
#pragma unroll
            for (int nt = 0; nt < 8; nt++) {
                int jb = jb0 + nt * 8;
#pragma unroll
                for (int q = 0; q < 4; q++) {
                    int s = q >> 1;
                    unsigned key = (__float_as_uint(acc[nt][q]) & ~0x1FFu) | (unsigned)(jb + (q & 1));
                    unsigned t = umx(bk1[s], key);
                    bk1[s] = umn(bk1[s], key);
                    bk2[s] = umn(bk2[s], t);
                }
            }
        }

        // ---- quad-merge u32 top-2, owners write per-half keys ----
#pragma unroll
        for (int s = 0; s < 2; s++) {
            unsigned k1 = bk1[s], k2 = bk2[s];
#pragma unroll
            for (int off = 1; off <= 2; off <<= 1) {
                unsigned o1 = __shfl_xor_sync(0xFFFFFFFFu, k1, off);
                unsigned o2 = __shfl_xor_sync(0xFFFFFFFFu, k2, off);
                unsigned t = umx(k1, o1);
                k1 = umn(k1, o1);
                k2 = umn(k2, umn(o2, t));
            }
            if ((lane & 3) == 0) {
                int r = mgrp * 16 + (lane >> 2) + s * 8;
                skey[(nh * 128 + r) * 2]     = k1;
                skey[(nh * 128 + r) * 2 + 1] = k2;
            }
        }
        __syncthreads();   // S3: both halves' top-2 keys in smem

        // ---- exact refine: 2 candidates per row (redundant half-merge) ----
        if (tid < 2 * TILE_M) {
            int r = tid >> 1;
            unsigned ka1 = skey[r * 2],         ka2 = skey[r * 2 + 1];
            unsigned kb1 = skey[(128 + r) * 2], kb2 = skey[(128 + r) * 2 + 1];
            unsigned m1 = umn(ka1, kb1);
            unsigned m2 = umn(umx(ka1, kb1), umn(ka2, kb2));
            int j = (int)(((tid & 1) ? m2 : m1) & 0x1FFu);

            const uint4* xh4 = (const uint4*)(sm + A_HI_OFF + r * ROWB);
            const uint4* xl4 = (const uint4*)(sm + A_LO_OFF + r * ROWB);
            const uint4* wh4 = (const uint4*)(sm + B_HI_OFF + j * ROWB);
            const uint4* wl4 = (const uint4*)(sm + B_LO_OFF + j * ROWB);
            float d = swsq[j];
#pragma unroll
            for (int c = 0; c < 8; c++) {
                uint4 hx = xh4[c], lx = xl4[c], hw = wh4[c], lw = wl4[c];
                const unsigned hxs[4] = {hx.x, hx.y, hx.z, hx.w};
                const unsigned lxs[4] = {lx.x, lx.y, lx.z, lx.w};
                const unsigned hws[4] = {hw.x, hw.y, hw.z, hw.w};
                const unsigned lws[4] = {lw.x, lw.y, lw.z, lw.w};
#pragma unroll
                for (int u = 0; u < 4; u++) {
                    float2 xa = h2f2(hxs[u]), xb = h2f2(lxs[u]);
                    float2 wa = h2f2(hws[u]), wb = h2f2(lws[u]);
                    float xx0 = xa.x + xb.x, xx1 = xa.y + xb.y;
                    float ww0 = wa.x + wb.x, ww1 = wa.y + wb.y;
                    d = fmaf(xx0, ww0, d);
                    d = fmaf(xx1, ww1, d);
                }
            }
            unsigned long long kd = packkey(d, j);
            unsigned long long ko = __shfl_xor_sync(0xFFFFFFFFu, kd, 1);
            if ((tid & 1) == 0) {
                unsigned long long kw = u64min(kd, ko);
                int jw = (int)(kw & 0xFFFFFFFFull);
                float dw;
                { unsigned m = (unsigned)(kw >> 32);
                  unsigned uu = (m & 0x80000000u) ? (m ^ 0x80000000u) : ~m;
                  dw = __uint_as_float(uu); }
                sj[r] = jw;
                loss_acc += dw + sxsq[r];
                atomicAdd(&scnt[jw], 1.0f);
            }
        }
        __syncthreads();   // S4: sj ready

        // ---- embed_sum scatter straight from fp32 registers ----
#pragma unroll
        for (int i = 0; i < 4; i++) {
            int idx = tid + i * TPB;
            int r = idx >> 4;
            int j = sj[r];
            red_add_v4(g_embed_sum + j * DIMV + (idx & 15) * 4, v[i].x, v[i].y, v[i].z, v[i].w);
        }
    }

    // ---- flush block-local accumulators ----
    atomicAdd(sloss, loss_acc);
    __syncthreads();
    if (scnt[tid] != 0.0f) atomicAdd(&g_counts[tid], scnt[tid]);
    if (tid == 0) atomicAdd(&g_loss_sum, *sloss);
}

// ---------------------------------------------------------------------------
// Kernel 3a: scalar reductions — n, per-code inv factor, loss, perplexity, cs
// ---------------------------------------------------------------------------
__global__ void vq_final1(const float* __restrict__ cs_in,
                          float* __restrict__ out, int nrows) {
    __shared__ float red[NEMB];
    int j = threadIdx.x;

    float counts = g_counts[j];
    float ncs = fmaf(0.99f, cs_in[j], 0.01f * counts);

    red[j] = ncs;
    __syncthreads();
#pragma unroll
    for (int off = NEMB / 2; off; off >>= 1) {
        if (j < off) red[j] += red[j + off];
        __syncthreads();
    }
    float n = red[0];
    __syncthreads();

    float csj = (ncs + 1e-5f) / (n + (float)NEMB * 1e-5f) * n;
    g_inv[j] = 1.0f / csj;
    out[2 + DIMV * NEMB + j] = ncs;  // new_cluster_size

    float p = counts / (float)nrows;
    red[j] = p * logf(p + 1e-10f);
    __syncthreads();
#pragma unroll
    for (int off = NEMB / 2; off; off >>= 1) {
        if (j < off) red[j] += red[j + off];
        __syncthreads();
    }
    if (j == 0) {
        out[1] = expf(-red[0]);
        out[0] = 0.25f * g_loss_sum / ((float)nrows * (float)DIMV);
    }
}

// ---------------------------------------------------------------------------
// Kernel 3b: parallel output writer — new_embed_avg + new_w
// ---------------------------------------------------------------------------
__global__ void vq_final2(const float* __restrict__ ea_in, float* __restrict__ out) {
    int gid = blockIdx.x * blockDim.x + threadIdx.x;   // 0 .. 32767
    int k = gid >> 9, j = gid & (NEMB - 1);
    float ea = fmaf(0.99f, ea_in[gid], 0.01f * g_embed_sum[j * DIMV + k]);
    const int EA_OFF = 2 + DIMV * NEMB + NEMB;
    out[EA_OFF + gid] = ea;              // new_embed_avg
    out[2 + gid] = ea * g_inv[j];        // new_w
}

// ---------------------------------------------------------------------------
extern "C" void kernel_launch(void* const* d_in, const int* in_sizes, int n_in,
                              void* d_out, int out_size) {
    const float* inp = (const float*)d_in[0];
    const float* w   = (const float*)d_in[1];
    const float* cs  = (const float*)d_in[2];
    const float* ea  = (const float*)d_in[3];
    int nrows = in_sizes[0] / DIMV;

    cudaFuncSetAttribute(vq_main, cudaFuncAttributeMaxDynamicSharedMemorySize, SMEM_BYTES);

    vq_init<<<72, 256>>>(w);
    vq_main<<<148, TPB, SMEM_BYTES>>>(inp, nrows);
    vq_final1<<<1, NEMB>>>(cs, (float*)d_out, nrows);
    vq_final2<<<DIMV * NEMB / 256, 256>>>(ea, (float*)d_out);
}

// round 12
// speedup vs baseline: 1.2324x; 1.0353x over previous
#include <cuda_runtime.h>
#include <cuda_fp16.h>
#include <math.h>

#define DIMV   64
#define NEMB   512
#define TPB    512
#define TILE_M 128
#define ROWB   144          // padded row stride: 72 fp16 (conflict-free ldmatrix)
#define POS_OFF 512.0f      // positivity offset folded into screen init

// ---------------- smem layout (bytes) ----------------
#define B_HI_OFF   0                          // 512 x 144B fp16 (-2w hi)
#define B_LO_OFF   (512*ROWB)                 // 73728
#define A_HI_OFF   (2*512*ROWB)               // 147456, 128 x 144B
#define A_LO_OFF   (A_HI_OFF + 128*ROWB)      // 165888
#define STAGE_OFF  (A_LO_OFF + 128*ROWB)      // 184320, raw fp32 tile 32KB
#define SWSQ_OFF   (STAGE_OFF + 32768)        // 217088, 512 f32 (exact, refine)
#define SCNT_OFF   (SWSQ_OFF + 2048)          // 512 f32
#define SWSQP_OFF  (SCNT_OFF + 2048)          // 512 f32 (wsq + POS_OFF, screen)
#define SKEY_OFF   (SWSQP_OFF + 2048)         // 2 x 128 x 2 u32 = 2048
#define SJ_OFF     (SKEY_OFF + 2048)          // 128 i32
#define SLOSS_OFF  (SJ_OFF + 512)
#define SMEM_BYTES (SLOSS_OFF + 16)           // 225808

// ---------------- device scratch ----------------
__device__ float          g_wsq[NEMB];
__device__ unsigned short g_w_hi[NEMB * DIMV];   // [j][k], -2w fp16 hi
__device__ unsigned short g_w_lo[NEMB * DIMV];   // fp16 residual
__device__ __align__(16) float g_embed_sum[NEMB * DIMV];  // code-major [j][k]
__device__ float          g_counts[NEMB];
__device__ float          g_inv[NEMB];
__device__ float          g_loss_sum;

// ---------------- helpers ----------------
__device__ __forceinline__ unsigned smem_u32(const void* p) {
    unsigned a;
    asm("{ .reg .u64 t; cvta.to.shared.u64 t, %1; cvt.u32.u64 %0, t; }" : "=r"(a) : "l"(p));
    return a;
}
__device__ __forceinline__ unsigned ford(float f) {
    unsigned u = __float_as_uint(f);
    unsigned m = (unsigned)((int)u >> 31) | 0x80000000u;
    return u ^ m;
}
__device__ __forceinline__ unsigned long long packkey(float v, int j) {
    return ((unsigned long long)ford(v) << 32) | (unsigned)j;
}
__device__ __forceinline__ unsigned umn(unsigned a, unsigned b) { return a < b ? a : b; }
__device__ __forceinline__ unsigned umx(unsigned a, unsigned b) { return a > b ? a : b; }
__device__ __forceinline__ unsigned long long u64min(unsigned long long a, unsigned long long b) {
    return a < b ? a : b;
}
__device__ __forceinline__ void ldm_x4(unsigned &r0, unsigned &r1, unsigned &r2, unsigned &r3,
                                       unsigned addr) {
    asm volatile("ldmatrix.sync.aligned.m8n8.x4.shared.b16 {%0,%1,%2,%3}, [%4];"
                 : "=r"(r0), "=r"(r1), "=r"(r2), "=r"(r3) : "r"(addr));
}
__device__ __forceinline__ void mma_fp16(float* d, const unsigned* a, unsigned b0, unsigned b1) {
    asm volatile("mma.sync.aligned.m16n8k16.row.col.f32.f16.f16.f32 "
                 "{%0,%1,%2,%3},{%4,%5,%6,%7},{%8,%9},{%0,%1,%2,%3};"
                 : "+f"(d[0]), "+f"(d[1]), "+f"(d[2]), "+f"(d[3])
                 : "r"(a[0]), "r"(a[1]), "r"(a[2]), "r"(a[3]), "r"(b0), "r"(b1));
}
__device__ __forceinline__ void red_add_v4(float* p, float a, float b, float c, float d) {
    asm volatile("red.global.add.v4.f32 [%0], {%1,%2,%3,%4};"
                 :: "l"(p), "f"(a), "f"(b), "f"(c), "f"(d) : "memory");
}
__device__ __forceinline__ void cp_async16(unsigned dst, const void* src) {
    asm volatile("cp.async.cg.shared.global [%0], [%1], 16;" :: "r"(dst), "l"(src) : "memory");
}
#define CP_COMMIT() asm volatile("cp.async.commit_group;" ::: "memory")
#define CP_WAIT0()  asm volatile("cp.async.wait_group 0;" ::: "memory")
__device__ __forceinline__ float2 h2f2(unsigned u) {
    __half2 h = *(__half2*)&u;
    return __half22float2(h);
}

// ---------------------------------------------------------------------------
// Kernel 1: coalesced init via smem transpose.
// Blocks 0-7: codebook (64 codes each). Blocks 8-71: zero embed_sum/counts.
// ---------------------------------------------------------------------------
__global__ void vq_init(const float* __restrict__ w) {
    const int b = blockIdx.x;
    const int tid = threadIdx.x;

    if (b >= 8) {
        int idx = (b - 8) * 256 + tid;       // 0..16383
        ((float2*)g_embed_sum)[idx] = make_float2(0.0f, 0.0f);
        if (idx < NEMB) g_counts[idx] = 0.0f;
        if (b == 8 && tid == 0) g_loss_sum = 0.0f;
        return;
    }

    __shared__ float t[DIMV][65];            // transposed tile, padded
#pragma unroll
    for (int i = 0; i < 16; i++) {
        int idx = tid + i * 256;             // 0..4095
        int k = idx >> 6, jl = idx & 63;
        t[k][jl] = w[k * NEMB + b * 64 + jl];
    }
    __syncthreads();

    const int jl = tid >> 2;
    const int kb = (tid & 3) * 16;
    const int j  = b * 64 + jl;

    unsigned hi[8], lo[8];
    float s = 0.0f;
#pragma unroll
    for (int c = 0; c < 16; c += 2) {
        float v0 = t[kb + c][jl], v1 = t[kb + c + 1][jl];
        s = fmaf(v0, v0, fmaf(v1, v1, s));
        float m0 = -2.0f * v0, m1 = -2.0f * v1;
        __half h0 = __float2half_rn(m0), h1 = __float2half_rn(m1);
        __half l0 = __float2half_rn(m0 - __half2float(h0));
        __half l1 = __float2half_rn(m1 - __half2float(h1));
        hi[c >> 1] = __half_as_ushort(h0) | ((unsigned)__half_as_ushort(h1) << 16);
        lo[c >> 1] = __half_as_ushort(l0) | ((unsigned)__half_as_ushort(l1) << 16);
    }
    uint4* dhi = (uint4*)(g_w_hi + j * DIMV + kb);
    uint4* dlo = (uint4*)(g_w_lo + j * DIMV + kb);
    dhi[0] = make_uint4(hi[0], hi[1], hi[2], hi[3]);
    dhi[1] = make_uint4(hi[4], hi[5], hi[6], hi[7]);
    dlo[0] = make_uint4(lo[0], lo[1], lo[2], lo[3]);
    dlo[1] = make_uint4(lo[4], lo[5], lo[6], lo[7]);

    s += __shfl_xor_sync(0xFFFFFFFFu, s, 1);
    s += __shfl_xor_sync(0xFFFFFFFFu, s, 2);
    if ((tid & 3) == 0) g_wsq[j] = s;
}

// ---------------------------------------------------------------------------
// Kernel 2: persistent main — fp16 HMMA screen (offset keys) + exact refine
// ---------------------------------------------------------------------------
__global__ __launch_bounds__(TPB, 1)
void vq_main(const float* __restrict__ inp, int nrows) {
    extern __shared__ __align__(1024) char sm[];
    const unsigned sbase = smem_u32(sm);
    const int tid  = threadIdx.x;
    const int lane = tid & 31;
    const int wid  = tid >> 5;
    const int mgrp = wid >> 1;      // 0..7 : row group of 16
    const int nh   = wid & 1;       // 0..1 : code half of 256

    float* swsq  = (float*)(sm + SWSQ_OFF);
    float* scnt  = (float*)(sm + SCNT_OFF);
    float* swsqp = (float*)(sm + SWSQP_OFF);
    unsigned* skey = (unsigned*)(sm + SKEY_OFF);
    int*   sj    = (int*)(sm + SJ_OFF);
    float* sloss = (float*)(sm + SLOSS_OFF);

    // --- stage B (-2w hi/lo fp16) into padded rows + swsq(+offset) + counters ---
    {
        const uint4* srcH = (const uint4*)g_w_hi;
        const uint4* srcL = (const uint4*)g_w_lo;
#pragma unroll
        for (int i = 0; i < 8; i++) {
            int idx = tid + i * TPB;        // 0..4095 : 16B chunk index
            int row = idx >> 3, c = idx & 7;
            *(uint4*)(sm + B_HI_OFF + row * ROWB + c * 16) = srcH[idx];
            *(uint4*)(sm + B_LO_OFF + row * ROWB + c * 16) = srcL[idx];
        }
        float wq = g_wsq[tid];
        swsq[tid]  = wq;
        swsqp[tid] = wq + POS_OFF;
        scnt[tid]  = 0.0f;
        if (tid == 0) *sloss = 0.0f;
    }

    // lane-fixed ldmatrix address offsets
    const unsigned aoff = (unsigned)((lane & 15) * ROWB + (lane >> 4) * 16);
    const unsigned boff = (unsigned)(((lane & 7) + ((lane >> 4) << 3)) * ROWB + ((lane >> 3) & 1) * 16);
    const unsigned aHbase = sbase + A_HI_OFF + (unsigned)(mgrp * 16 * ROWB) + aoff;
    const unsigned bHbase = sbase + B_HI_OFF + (unsigned)(nh * 256 * ROWB) + boff;

    float loss_acc = 0.0f;
    const int nchunks = nrows / TILE_M;

    // ---- prefetch first tile into staging ----
    {
        const float4* src = (const float4*)inp + (size_t)blockIdx.x * (TILE_M * DIMV / 4);
#pragma unroll
        for (int i = 0; i < 4; i++)
            cp_async16(sbase + STAGE_OFF + (tid + i * TPB) * 16, src + tid + i * TPB);
        CP_COMMIT();
    }

    for (int tile = blockIdx.x; tile < nchunks; tile += gridDim.x) {
        CP_WAIT0();
        __syncthreads();   // S1: staging visible; prev refine/scatter done

        // ---- convert x -> fp16 hi/lo in smem (x kept in v regs) ----
        float4 v[4];
        const float4* stg = (const float4*)(sm + STAGE_OFF);
#pragma unroll
        for (int i = 0; i < 4; i++) {
            int idx = tid + i * TPB;
            float4 x = stg[idx];
            v[i] = x;
            __half h0 = __float2half_rn(x.x), h1 = __float2half_rn(x.y);
            __half h2 = __float2half_rn(x.z), h3 = __float2half_rn(x.w);
            __half l0 = __float2half_rn(x.x - __half2float(h0));
            __half l1 = __float2half_rn(x.y - __half2float(h1));
            __half l2 = __float2half_rn(x.z - __half2float(h2));
            __half l3 = __float2half_rn(x.w - __half2float(h3));
            unsigned hw0 = __half_as_ushort(h0) | ((unsigned)__half_as_ushort(h1) << 16);
            unsigned hw1 = __half_as_ushort(h2) | ((unsigned)__half_as_ushort(h3) << 16);
            unsigned lw0 = __half_as_ushort(l0) | ((unsigned)__half_as_ushort(l1) << 16);
            unsigned lw1 = __half_as_ushort(l2) | ((unsigned)__half_as_ushort(l3) << 16);
            unsigned long long hw = ((unsigned long long)hw1 << 32) | hw0;
            unsigned long long lw = ((unsigned long long)lw1 << 32) | lw0;
            int row = idx >> 4, kc = idx & 15;
            *(unsigned long long*)(sm + A_HI_OFF + row * ROWB + kc * 8) = hw;
            *(unsigned long long*)(sm + A_LO_OFF + row * ROWB + kc * 8) = lw;
        }
        __syncthreads();   // S2: A smem ready; staging reads done

        // ---- prefetch next tile (overlaps MMA) ----
        {
            int nxt = tile + gridDim.x;
            if (nxt < nchunks) {
                const float4* src = (const float4*)inp + (size_t)nxt * (TILE_M * DIMV / 4);
#pragma unroll
                for (int i = 0; i < 4; i++)
                    cp_async16(sbase + STAGE_OFF + (tid + i * TPB) * 16, src + tid + i * TPB);
            }
            CP_COMMIT();
        }

        // ---- load A hi fragments ----
        unsigned Ah[4][4];
#pragma unroll
        for (int ks = 0; ks < 4; ks++)
            ldm_x4(Ah[ks][0], Ah[ks][1], Ah[ks][2], Ah[ks][3], aHbase + (unsigned)(ks * 32));

        // ---- single-pass screen GEMM; positive-key top-2 (pure IMNMX/LOP3) ----
        unsigned bk1[2] = {0xFFFFFFFFu, 0xFFFFFFFFu};
        unsigned bk2[2] = {0xFFFFFFFFu, 0xFFFFFFFFu};

#pragma unroll
        for (int chunk = 0; chunk < 4; chunk++) {
            float acc[8][4];
            int jb0 = nh * 256 + chunk * 64 + (lane & 3) * 2;
#pragma unroll
            for (int nt = 0; nt < 8; nt++) {
                float2 wq = *(float2*)(swsqp + jb0 + nt * 8);
                acc[nt][0] = wq.x; acc[nt][1] = wq.y;
                acc[nt][2] = wq.x; acc[nt][3] = wq.y;
            }
            unsigned bc = (unsigned)(chunk * 64 * ROWB);
#pragma unroll
            for (int ks = 0; ks < 4; ks++) {
                unsigned B0[4][4];
#pragma unroll
                for (int pr = 0; pr < 4; pr++) {
                    unsigned off = bc + (unsigned)(pr * 16 * ROWB + ks * 32);
                    ldm_x4(B0[pr][0], B0[pr][1], B0[pr][2], B0[pr][3], bHbase + off);
                }
#pragma unroll
                for (int pr = 0; pr < 4; pr++) {
                    mma_fp16(acc[2*pr],   Ah[ks], B0[pr][0], B0[pr][1]);
                    mma_fp16(acc[2*pr+1], Ah[ks], B0[pr][2], B0[pr][3]);
                }
            }
            // fold: values = d + POS_OFF > 0 -> bits order as unsigned
#pragma unroll
            for (int nt = 0; nt < 8; nt++) {
                int jb = jb0 + nt * 8;
#pragma unroll
                for (int q = 0; q < 4; q++) {
                    int s = q >> 1;
                    unsigned key = (__float_as_uint(acc[nt][q]) & ~0x1FFu) | (unsigned)(jb + (q & 1));
                    unsigned t = umx(bk1[s], key);
                    bk1[s] = umn(bk1[s], key);
                    bk2[s] = umn(bk2[s], t);
                }
            }
        }

        // ---- quad-merge u32 top-2, owners write per-half keys ----
#pragma unroll
        for (int s = 0; s < 2; s++) {
            unsigned k1 = bk1[s], k2 = bk2[s];
#pragma unroll
            for (int off = 1; off <= 2; off <<= 1) {
                unsigned o1 = __shfl_xor_sync(0xFFFFFFFFu, k1, off);
                unsigned o2 = __shfl_xor_sync(0xFFFFFFFFu, k2, off);
                unsigned t = umx(k1, o1);
                k1 = umn(k1, o1);
                k2 = umn(k2, umn(o2, t));
            }
            if ((lane & 3) == 0) {
                int r = mgrp * 16 + (lane >> 2) + s * 8;
                skey[(nh * 128 + r) * 2]     = k1;
                skey[(nh * 128 + r) * 2 + 1] = k2;
            }
        }
        __syncthreads();   // S3: both halves' top-2 keys in smem

        // ---- exact refine: 2 candidates per row; also computes ||x||^2 ----
        if (tid < 2 * TILE_M) {
            int r = tid >> 1;
            unsigned ka1 = skey[r * 2],         ka2 = skey[r * 2 + 1];
            unsigned kb1 = skey[(128 + r) * 2], kb2 = skey[(128 + r) * 2 + 1];
            unsigned m1 = umn(ka1, kb1);
            unsigned m2 = umn(umx(ka1, kb1), umn(ka2, kb2));
            int j = (int)(((tid & 1) ? m2 : m1) & 0x1FFu);

            const uint4* xh4 = (const uint4*)(sm + A_HI_OFF + r * ROWB);
            const uint4* xl4 = (const uint4*)(sm + A_LO_OFF + r * ROWB);
            const uint4* wh4 = (const uint4*)(sm + B_HI_OFF + j * ROWB);
            const uint4* wl4 = (const uint4*)(sm + B_LO_OFF + j * ROWB);
            float d = swsq[j];
            float e = 0.0f;                       // ||x||^2
#pragma unroll
            for (int c = 0; c < 8; c++) {
                uint4 hx = xh4[c], lx = xl4[c], hw = wh4[c], lw = wl4[c];
                const unsigned hxs[4] = {hx.x, hx.y, hx.z, hx.w};
                const unsigned lxs[4] = {lx.x, lx.y, lx.z, lx.w};
                const unsigned hws[4] = {hw.x, hw.y, hw.z, hw.w};
                const unsigned lws[4] = {lw.x, lw.y, lw.z, lw.w};
#pragma unroll
                for (int u = 0; u < 4; u++) {
                    float2 xa = h2f2(hxs[u]), xb = h2f2(lxs[u]);
                    float2 wa = h2f2(hws[u]), wb = h2f2(lws[u]);
                    float xx0 = xa.x + xb.x, xx1 = xa.y + xb.y;
                    float ww0 = wa.x + wb.x, ww1 = wa.y + wb.y;
                    d = fmaf(xx0, ww0, d);
                    d = fmaf(xx1, ww1, d);
                    e = fmaf(xx0, xx0, e);
                    e = fmaf(xx1, xx1, e);
                }
            }
            unsigned long long kd = packkey(d, j);
            unsigned long long ko = __shfl_xor_sync(0xFFFFFFFFu, kd, 1);
            if ((tid & 1) == 0) {
                unsigned long long kw = u64min(kd, ko);
                int jw = (int)(kw & 0xFFFFFFFFull);
                float dw;
                { unsigned m = (unsigned)(kw >> 32);
                  unsigned uu = (m & 0x80000000u) ? (m ^ 0x80000000u) : ~m;
                  dw = __uint_as_float(uu); }
                sj[r] = jw;
                loss_acc += dw + e;
                atomicAdd(&scnt[jw], 1.0f);
            }
        }
        __syncthreads();   // S4: sj ready

        // ---- embed_sum scatter straight from fp32 registers ----
#pragma unroll
        for (int i = 0; i < 4; i++) {
            int idx = tid + i * TPB;
            int r = idx >> 4;
            int j = sj[r];
            red_add_v4(g_embed_sum + j * DIMV + (idx & 15) * 4, v[i].x, v[i].y, v[i].z, v[i].w);
        }
    }

    // ---- flush block-local accumulators ----
    atomicAdd(sloss, loss_acc);
    __syncthreads();
    if (scnt[tid] != 0.0f) atomicAdd(&g_counts[tid], scnt[tid]);
    if (tid == 0) atomicAdd(&g_loss_sum, *sloss);
}

// ---------------------------------------------------------------------------
// Kernel 3a: scalar reductions — n, per-code inv factor, loss, perplexity, cs
// ---------------------------------------------------------------------------
__global__ void vq_final1(const float* __restrict__ cs_in,
                          float* __restrict__ out, int nrows) {
    __shared__ float red[NEMB];
    int j = threadIdx.x;

    float counts = g_counts[j];
    float ncs = fmaf(0.99f, cs_in[j], 0.01f * counts);

    red[j] = ncs;
    __syncthreads();
#pragma unroll
    for (int off = NEMB / 2; off; off >>= 1) {
        if (j < off) red[j] += red[j + off];
        __syncthreads();
    }
    float n = red[0];
    __syncthreads();

    float csj = (ncs + 1e-5f) / (n + (float)NEMB * 1e-5f) * n;
    g_inv[j] = 1.0f / csj;
    out[2 + DIMV * NEMB + j] = ncs;  // new_cluster_size

    float p = counts / (float)nrows;
    red[j] = p * logf(p + 1e-10f);
    __syncthreads();
#pragma unroll
    for (int off = NEMB / 2; off; off >>= 1) {
        if (j < off) red[j] += red[j + off];
        __syncthreads();
    }
    if (j == 0) {
        out[1] = expf(-red[0]);
        out[0] = 0.25f * g_loss_sum / ((float)nrows * (float)DIMV);
    }
}

// ---------------------------------------------------------------------------
// Kernel 3b: parallel output writer — new_embed_avg + new_w
// ---------------------------------------------------------------------------
__global__ void vq_final2(const float* __restrict__ ea_in, float* __restrict__ out) {
    int gid = blockIdx.x * blockDim.x + threadIdx.x;   // 0 .. 32767
    int k = gid >> 9, j = gid & (NEMB - 1);
    float ea = fmaf(0.99f, ea_in[gid], 0.01f * g_embed_sum[j * DIMV + k]);
    const int EA_OFF = 2 + DIMV * NEMB + NEMB;
    out[EA_OFF + gid] = ea;              // new_embed_avg
    out[2 + gid] = ea * g_inv[j];        // new_w
}

// ---------------------------------------------------------------------------
extern "C" void kernel_launch(void* const* d_in, const int* in_sizes, int n_in,
                              void* d_out, int out_size) {
    const float* inp = (const float*)d_in[0];
    const float* w   = (const float*)d_in[1];
    const float* cs  = (const float*)d_in[2];
    const float* ea  = (const float*)d_in[3];
    int nrows = in_sizes[0] / DIMV;

    cudaFuncSetAttribute(vq_main, cudaFuncAttributeMaxDynamicSharedMemorySize, SMEM_BYTES);

    vq_init<<<72, 256>>>(w);
    vq_main<<<148, TPB, SMEM_BYTES>>>(inp, nrows);
    vq_final1<<<1, NEMB>>>(cs, (float*)d_out, nrows);
    vq_final2<<<DIMV * NEMB / 256, 256>>>(ea, (float*)d_out);
}